// round 2
// baseline (speedup 1.0000x reference)
#include <cuda_runtime.h>

// ---------------------------------------------------------------------------
// Attention_18476949308128 — round 2: 128x128x8 SIMT GEMM + fused attention
// B=2, S=2048, D_EMBED=D_MODEL=1024, H=16, d_k=64
// Pipeline:
//   1) Q/K/V projections       gemm_nt128 (NT + bias)
//   2) scores_exp              E = exp(QK^T + maskadd), rowsum  (fused)
//   3) rescale_attnv           attn = E/rowsum (in place) ; O = attn @ V
//   4) out projection          gemm_nt128
// ---------------------------------------------------------------------------

// Scratch (static __device__ globals: allocation-free per harness rules)
__device__ float g_Q[4096 * 1024];
__device__ float g_K[4096 * 1024];
__device__ float g_V[4096 * 1024];
__device__ float g_C[4096 * 1024];      // blended, [b, q, h, d] == [4096,1024]
__device__ float g_rowsum[65536];
__device__ float g_attn[134217728];      // fallback if attn not in d_out

// ============================================================================
// 128x128 tile, BK=8, double-buffered, 8x8 microtile. C = A @ B^T + bias
// A: [M,K] row-major (lda), B: [N,K] row-major (ldb), C: [M,N] (ldc)
// ============================================================================
__global__ __launch_bounds__(256, 2) void gemm_nt128(
    const float* __restrict__ A, const float* __restrict__ B,
    float* __restrict__ C, const float* __restrict__ bias,
    int K, int lda, int ldb, int ldc)
{
    __shared__ float As[2][8][128];
    __shared__ float Bs[2][8][128];

    int t  = threadIdx.x;
    int m0 = blockIdx.y * 128;
    int n0 = blockIdx.x * 128;
    int lr = t >> 1;             // 0..127
    int lc = (t & 1) * 4;        // 0 or 4
    int tx = t & 15, ty = t >> 4;

    const float* Aptr = A + (long)(m0 + lr) * lda + lc;
    const float* Bptr = B + (long)(n0 + lr) * ldb + lc;

    float4 a4 = *(const float4*)Aptr;
    float4 b4 = *(const float4*)Bptr;
    As[0][lc + 0][lr] = a4.x; As[0][lc + 1][lr] = a4.y;
    As[0][lc + 2][lr] = a4.z; As[0][lc + 3][lr] = a4.w;
    Bs[0][lc + 0][lr] = b4.x; Bs[0][lc + 1][lr] = b4.y;
    Bs[0][lc + 2][lr] = b4.z; Bs[0][lc + 3][lr] = b4.w;
    __syncthreads();

    float acc[8][8] = {};
    int buf = 0;

    for (int k0 = 8; k0 < K; k0 += 8) {
        a4 = *(const float4*)(Aptr + k0);
        b4 = *(const float4*)(Bptr + k0);
#pragma unroll
        for (int k = 0; k < 8; k++) {
            float4 A0 = *(const float4*)&As[buf][k][ty * 4];
            float4 A1 = *(const float4*)&As[buf][k][ty * 4 + 64];
            float4 B0 = *(const float4*)&Bs[buf][k][tx * 4];
            float4 B1 = *(const float4*)&Bs[buf][k][tx * 4 + 64];
            float av[8] = {A0.x, A0.y, A0.z, A0.w, A1.x, A1.y, A1.z, A1.w};
            float bv[8] = {B0.x, B0.y, B0.z, B0.w, B1.x, B1.y, B1.z, B1.w};
#pragma unroll
            for (int i = 0; i < 8; i++)
#pragma unroll
                for (int j = 0; j < 8; j++)
                    acc[i][j] += av[i] * bv[j];
        }
        int nb = buf ^ 1;
        As[nb][lc + 0][lr] = a4.x; As[nb][lc + 1][lr] = a4.y;
        As[nb][lc + 2][lr] = a4.z; As[nb][lc + 3][lr] = a4.w;
        Bs[nb][lc + 0][lr] = b4.x; Bs[nb][lc + 1][lr] = b4.y;
        Bs[nb][lc + 2][lr] = b4.z; Bs[nb][lc + 3][lr] = b4.w;
        __syncthreads();
        buf = nb;
    }
#pragma unroll
    for (int k = 0; k < 8; k++) {
        float4 A0 = *(const float4*)&As[buf][k][ty * 4];
        float4 A1 = *(const float4*)&As[buf][k][ty * 4 + 64];
        float4 B0 = *(const float4*)&Bs[buf][k][tx * 4];
        float4 B1 = *(const float4*)&Bs[buf][k][tx * 4 + 64];
        float av[8] = {A0.x, A0.y, A0.z, A0.w, A1.x, A1.y, A1.z, A1.w};
        float bv[8] = {B0.x, B0.y, B0.z, B0.w, B1.x, B1.y, B1.z, B1.w};
#pragma unroll
        for (int i = 0; i < 8; i++)
#pragma unroll
            for (int j = 0; j < 8; j++)
                acc[i][j] += av[i] * bv[j];
    }

#pragma unroll
    for (int jj = 0; jj < 2; jj++) {
        float4 bvec = *(const float4*)(bias + n0 + tx * 4 + jj * 64);
#pragma unroll
        for (int i = 0; i < 8; i++) {
            int row = m0 + ((i < 4) ? ty * 4 + i : 64 + ty * 4 + (i - 4));
            float4 v;
            v.x = acc[i][jj * 4 + 0] + bvec.x;
            v.y = acc[i][jj * 4 + 1] + bvec.y;
            v.z = acc[i][jj * 4 + 2] + bvec.z;
            v.w = acc[i][jj * 4 + 3] + bvec.w;
            *(float4*)(C + (long)row * ldc + n0 + tx * 4 + jj * 64) = v;
        }
    }
}

// ============================================================================
// scores_exp: per (qtile, bh): E[q, k] = exp(Q·K^T + (1-mask)*NEG), rowsum
// block = 128 q-rows, sweeps all 2048 k in 16 tiles of 128. 256 threads.
// ============================================================================
__global__ __launch_bounds__(256) void scores_exp(
    const float* __restrict__ Q, const float* __restrict__ Kp,
    const float* __restrict__ mask,
    float* __restrict__ E, float* __restrict__ rowsum)
{
    extern __shared__ float smem[];
    float* Qs   = smem;                    // [64][128]
    float* Ks   = smem + 64 * 128;         // [64][132]
    float* part = Ks + 64 * 132;           // [16][128]

    int t  = threadIdx.x;
    int qt = blockIdx.x, bh = blockIdx.y;
    int b = bh >> 4, h = bh & 15;
    const float* Qh   = Q  + (long)b * 2048 * 1024 + h * 64;
    const float* Kh   = Kp + (long)b * 2048 * 1024 + h * 64;
    float*       Ebh  = E  + ((long)bh * 2048 + qt * 128) * 2048;
    const float* mrow = mask + (long)b * 2048;

    // load Q tile [128 q][64 d] transposed -> Qs[d][q]
    {
        int row = t >> 1;
        int d0  = (t & 1) * 32;
        const float* src = Qh + (long)(qt * 128 + row) * 1024 + d0;
#pragma unroll
        for (int j = 0; j < 8; j++) {
            float4 v = *(const float4*)(src + j * 4);
            Qs[(d0 + j * 4 + 0) * 128 + row] = v.x;
            Qs[(d0 + j * 4 + 1) * 128 + row] = v.y;
            Qs[(d0 + j * 4 + 2) * 128 + row] = v.z;
            Qs[(d0 + j * 4 + 3) * 128 + row] = v.w;
        }
    }
    __syncthreads();

    int tx = t & 15, ty = t >> 4;
    float rs[8] = {};

    for (int kt = 0; kt < 16; kt++) {
        // load K tile [128 k][64 d] transposed -> Ks[d][k]
        {
            int row = t >> 1;
            int d0  = (t & 1) * 32;
            const float* src = Kh + (long)(kt * 128 + row) * 1024 + d0;
#pragma unroll
            for (int j = 0; j < 8; j++) {
                float4 v = *(const float4*)(src + j * 4);
                Ks[(d0 + j * 4 + 0) * 132 + row] = v.x;
                Ks[(d0 + j * 4 + 1) * 132 + row] = v.y;
                Ks[(d0 + j * 4 + 2) * 132 + row] = v.z;
                Ks[(d0 + j * 4 + 3) * 132 + row] = v.w;
            }
        }
        __syncthreads();

        float acc[8][8] = {};
#pragma unroll
        for (int d = 0; d < 64; d++) {
            float4 A0 = *(const float4*)&Qs[d * 128 + ty * 4];
            float4 A1 = *(const float4*)&Qs[d * 128 + ty * 4 + 64];
            float4 B0 = *(const float4*)&Ks[d * 132 + tx * 4];
            float4 B1 = *(const float4*)&Ks[d * 132 + tx * 4 + 64];
            float av[8] = {A0.x, A0.y, A0.z, A0.w, A1.x, A1.y, A1.z, A1.w};
            float bv[8] = {B0.x, B0.y, B0.z, B0.w, B1.x, B1.y, B1.z, B1.w};
#pragma unroll
            for (int i = 0; i < 8; i++)
#pragma unroll
                for (int j = 0; j < 8; j++)
                    acc[i][j] += av[i] * bv[j];
        }

        // exp + mask + store E + rowsum partials
#pragma unroll
        for (int jj = 0; jj < 2; jj++) {
            int cbase = kt * 128 + tx * 4 + jj * 64;
            float m0v = (1.0f - mrow[cbase + 0]) * (-1e9f);
            float m1v = (1.0f - mrow[cbase + 1]) * (-1e9f);
            float m2v = (1.0f - mrow[cbase + 2]) * (-1e9f);
            float m3v = (1.0f - mrow[cbase + 3]) * (-1e9f);
#pragma unroll
            for (int i = 0; i < 8; i++) {
                int row = (i < 4) ? ty * 4 + i : 64 + ty * 4 + (i - 4);
                float4 ev;
                ev.x = __expf(acc[i][jj * 4 + 0] + m0v);
                ev.y = __expf(acc[i][jj * 4 + 1] + m1v);
                ev.z = __expf(acc[i][jj * 4 + 2] + m2v);
                ev.w = __expf(acc[i][jj * 4 + 3] + m3v);
                rs[i] += (ev.x + ev.y) + (ev.z + ev.w);
                *(float4*)(Ebh + (long)row * 2048 + cbase) = ev;
            }
        }
        __syncthreads();   // before Ks overwrite
    }

    // deterministic rowsum reduction
#pragma unroll
    for (int i = 0; i < 8; i++) {
        int row = (i < 4) ? ty * 4 + i : 64 + ty * 4 + (i - 4);
        part[tx * 128 + row] = rs[i];
    }
    __syncthreads();
    if (t < 128) {
        float s = 0.f;
#pragma unroll
        for (int x = 0; x < 16; x++) s += part[x * 128 + t];
        rowsum[(long)bh * 2048 + qt * 128 + t] = s;
    }
}

// ============================================================================
// rescale_attnv: attn = E / rowsum (in place), O[128,64] += attn @ V
// block = (qtile, bh), 256 threads, thread tile 8q x 4d
// ============================================================================
__global__ __launch_bounds__(256) void rescale_attnv(
    float* __restrict__ E, const float* __restrict__ V,
    const float* __restrict__ rowsum, float* __restrict__ Cc)
{
    extern __shared__ float smem[];
    float* Es   = smem;                  // [128][132]
    float* Vs   = Es + 128 * 132;        // [128][64]
    float* invs = Vs + 128 * 64;         // [128]

    int t  = threadIdx.x;
    int qt = blockIdx.x, bh = blockIdx.y;
    int b = bh >> 4, h = bh & 15;
    float*       Ebh = E + ((long)bh * 2048 + qt * 128) * 2048;
    const float* Vh  = V + (long)b * 2048 * 1024 + h * 64;
    float*       Ch  = Cc + ((long)b * 2048 + qt * 128) * 1024 + h * 64;

    if (t < 128) invs[t] = 1.0f / rowsum[(long)bh * 2048 + qt * 128 + t];
    __syncthreads();

    int tx = t & 15, ty = t >> 4;
    float acc[8][4] = {};

    for (int kt = 0; kt < 16; kt++) {
        // V tile [128 k][64 d] natural layout
        {
            int row = t >> 1, c0 = (t & 1) * 32;
            const float* src = Vh + (long)(kt * 128 + row) * 1024 + c0;
#pragma unroll
            for (int j = 0; j < 8; j++)
                *(float4*)&Vs[row * 64 + c0 + j * 4] = *(const float4*)(src + j * 4);
        }
        // E tile: read, scale, write back (final attn), stage in smem
        {
            int row = t >> 1, c0 = (t & 1) * 64;
            float inv = invs[row];
            float* gp = Ebh + (long)row * 2048 + kt * 128 + c0;
#pragma unroll
            for (int j = 0; j < 16; j++) {
                float4 v = *(const float4*)(gp + j * 4);
                v.x *= inv; v.y *= inv; v.z *= inv; v.w *= inv;
                *(float4*)(gp + j * 4) = v;
                *(float4*)&Es[row * 132 + c0 + j * 4] = v;
            }
        }
        __syncthreads();

#pragma unroll 2
        for (int k = 0; k < 128; k += 2) {
            float4 v0 = *(const float4*)&Vs[k * 64 + tx * 4];
            float4 v1 = *(const float4*)&Vs[(k + 1) * 64 + tx * 4];
#pragma unroll
            for (int i = 0; i < 8; i++) {
                float2 e = *(const float2*)&Es[(ty * 8 + i) * 132 + k];
                acc[i][0] += e.x * v0.x + e.y * v1.x;
                acc[i][1] += e.x * v0.y + e.y * v1.y;
                acc[i][2] += e.x * v0.z + e.y * v1.z;
                acc[i][3] += e.x * v0.w + e.y * v1.w;
            }
        }
        __syncthreads();
    }

#pragma unroll
    for (int i = 0; i < 8; i++) {
        float4 o;
        o.x = acc[i][0]; o.y = acc[i][1]; o.z = acc[i][2]; o.w = acc[i][3];
        *(float4*)(Ch + (long)(ty * 8 + i) * 1024 + tx * 4) = o;
    }
}

// ============================================================================
extern "C" void kernel_launch(void* const* d_in, const int* in_sizes, int n_in,
                              void* d_out, int out_size)
{
    (void)in_sizes; (void)n_in;
    const float* query        = (const float*)d_in[0];
    const float* input_embeds = (const float*)d_in[1];
    const float* mask         = (const float*)d_in[2];
    const float* wq_w = (const float*)d_in[3];
    const float* wq_b = (const float*)d_in[4];
    const float* wk_w = (const float*)d_in[5];
    const float* wk_b = (const float*)d_in[6];
    const float* wv_w = (const float*)d_in[7];
    const float* wv_b = (const float*)d_in[8];
    const float* wo_w = (const float*)d_in[9];
    const float* wo_b = (const float*)d_in[10];
    float* out = (float*)d_out;

    float *Q, *K, *V, *Cc, *rowsum, *attn_scratch;
    cudaGetSymbolAddress((void**)&Q,  g_Q);
    cudaGetSymbolAddress((void**)&K,  g_K);
    cudaGetSymbolAddress((void**)&V,  g_V);
    cudaGetSymbolAddress((void**)&Cc, g_C);
    cudaGetSymbolAddress((void**)&rowsum, g_rowsum);
    cudaGetSymbolAddress((void**)&attn_scratch, g_attn);

    const long OUT_E  = 4194304L;    // 2*2048*1024
    const long ATTN_E = 134217728L;  // 2*16*2048*2048
    float* attn = ((long)out_size >= OUT_E + ATTN_E) ? (out + OUT_E) : attn_scratch;

    const int SMEM_SCORES  = (64 * 128 + 64 * 132 + 16 * 128) * 4;   // 74752
    const int SMEM_RESCALE = (128 * 132 + 128 * 64 + 128) * 4;       // 100864
    cudaFuncSetAttribute(scores_exp, cudaFuncAttributeMaxDynamicSharedMemorySize, SMEM_SCORES);
    cudaFuncSetAttribute(rescale_attnv, cudaFuncAttributeMaxDynamicSharedMemorySize, SMEM_RESCALE);

    dim3 blk(256);

    // 1) Projections: [4096,1024] = X @ W^T + b
    dim3 gProj(1024 / 128, 4096 / 128);
    gemm_nt128<<<gProj, blk>>>(query,        wq_w, Q, wq_b, 1024, 1024, 1024, 1024);
    gemm_nt128<<<gProj, blk>>>(input_embeds, wk_w, K, wk_b, 1024, 1024, 1024, 1024);
    gemm_nt128<<<gProj, blk>>>(input_embeds, wv_w, V, wv_b, 1024, 1024, 1024, 1024);

    // 2) E = exp(scores + maskadd), rowsum
    dim3 gS(16, 32);
    scores_exp<<<gS, blk, SMEM_SCORES>>>(Q, K, mask, attn, rowsum);

    // 3) attn = E/rowsum (in place), O = attn @ V  -> Cc [b,q,h,d]
    rescale_attnv<<<gS, blk, SMEM_RESCALE>>>(attn, V, rowsum, Cc);

    // 4) out = concat @ wo^T + wo_b
    gemm_nt128<<<gProj, blk>>>(Cc, wo_w, out, wo_b, 1024, 1024, 1024, 1024);
}